// round 9
// baseline (speedup 1.0000x reference)
#include <cuda_runtime.h>
#include <cuda_fp16.h>

#define NN    100000
#define NE    3200000
#define ETOT  (NE + NN)
#define SCAN_B 512
#define NBLK   ((NN + SCAN_B - 1) / SCAN_B)   // 196

// ---------------- scratch (device globals; allocation-free) ----------------
// Node record, layers 1-2: stride 128B = [h fp16 x32 (64B) | asrc fp32 x2 | pad]
// Node record, layer  3 : stride  64B = [h fp16 x16 (32B) | asrc fp32 x1 | pad]
__device__ __align__(128) uint4 g_rec[NN * 8];    // 12.8 MB
__device__ __align__(16) float g_agg[NN * 32];    // aggregated output, layers 1-2
__device__ __align__(8)  float g_adst[NN * 2];    // alpha_dst per node per head
__device__ __align__(8)  float g_sum[NN * 2];     // softmax denominator (layers 1-2)
__device__ int g_csr_src[ETOT];                   // src ids grouped by dst
__device__ int g_cnt[NN];
__device__ int g_off[NN + 1];
__device__ int g_cur[NN];
__device__ int g_bsum[NBLK];
__device__ int g_boff[NBLK];
__device__ int g_is64;

// ---------------- probe dtype (block 0) + zero counts (all blocks) ----------
__global__ __launch_bounds__(256) void probe_zero(const int* __restrict__ ei32, int n) {
    int i = blockIdx.x * 256 + threadIdx.x;
    if (i < n) g_cnt[i] = 0;
    if (blockIdx.x == 0) {
        __shared__ int nz;
        if (threadIdx.x == 0) nz = 0;
        __syncthreads();
        // int64 arrays of small values have zero odd 32-bit words
        if (ei32[2 * threadIdx.x + 1] != 0) atomicOr(&nz, 1);
        __syncthreads();
        if (threadIdx.x == 0) g_is64 = (nz == 0) ? 1 : 0;
    }
}

// ---------------- dst histogram straight from edge_index --------------------
__global__ __launch_bounds__(256) void hist(const void* __restrict__ ei, int E, int n) {
    int i = blockIdx.x * 256 + threadIdx.x;
    int d;
    if (i < E) {
        d = g_is64 ? (int)((const long long*)ei)[E + i] : ((const int*)ei)[E + i];
    } else if (i < E + n) {
        d = i - E;
    } else return;
    atomicAdd(&g_cnt[d], 1);
}

// ---------------- 3-kernel exclusive scan of g_cnt -> g_off -----------------
__global__ __launch_bounds__(SCAN_B) void scan1(int n) {
    __shared__ int sm[SCAN_B];
    int t = threadIdx.x, i = blockIdx.x * SCAN_B + t;
    int v = (i < n) ? g_cnt[i] : 0;
    sm[t] = v; __syncthreads();
#pragma unroll
    for (int o = 1; o < SCAN_B; o <<= 1) {
        int x = (t >= o) ? sm[t - o] : 0;
        __syncthreads();
        sm[t] += x;
        __syncthreads();
    }
    if (i < n) g_off[i] = sm[t] - v;
    if (t == SCAN_B - 1) g_bsum[blockIdx.x] = sm[t];
}

__global__ void scan2(int nb) {
    __shared__ int sm[256];
    int t = threadIdx.x;
    int v = (t < nb) ? g_bsum[t] : 0;
    sm[t] = v; __syncthreads();
#pragma unroll
    for (int o = 1; o < 256; o <<= 1) {
        int x = (t >= o) ? sm[t - o] : 0;
        __syncthreads();
        sm[t] += x;
        __syncthreads();
    }
    if (t < nb) g_boff[t] = sm[t] - v;
}

__global__ __launch_bounds__(256) void scan3(int n, int etot) {
    int i = blockIdx.x * 256 + threadIdx.x;
    if (i < n) {
        int v = g_off[i] + g_boff[i / SCAN_B];
        g_off[i] = v;
        g_cur[i] = v;
    }
    if (i == 0) g_off[n] = etot;
}

// ---------------- scatter straight from edge_index --------------------------
__global__ __launch_bounds__(256) void scatter(const void* __restrict__ ei, int E, int n) {
    int i = blockIdx.x * 256 + threadIdx.x;
    int s, d;
    if (i < E) {
        if (g_is64) {
            const long long* p = (const long long*)ei;
            s = (int)p[i]; d = (int)p[E + i];
        } else {
            const int* p = (const int*)ei;
            s = p[i]; d = p[E + i];
        }
    } else if (i < E + n) {
        s = d = i - E;
    } else return;
    int p = atomicAdd(&g_cur[d], 1);
    g_csr_src[p] = s;
}

// ---------------- record writer: h fp16 + asrc fp32 -------------------------
template <int OUT>
__device__ __forceinline__ void store_record(char* row, const float* h,
                                             float a0, float a1) {
#pragma unroll
    for (int k = 0; k < OUT / 8; k++) {
        __half2 p0 = __floats2half2_rn(h[8 * k + 0], h[8 * k + 1]);
        __half2 p1 = __floats2half2_rn(h[8 * k + 2], h[8 * k + 3]);
        __half2 p2 = __floats2half2_rn(h[8 * k + 4], h[8 * k + 5]);
        __half2 p3 = __floats2half2_rn(h[8 * k + 6], h[8 * k + 7]);
        uint4 u;
        u.x = *(unsigned*)&p0; u.y = *(unsigned*)&p1;
        u.z = *(unsigned*)&p2; u.w = *(unsigned*)&p3;
        ((uint4*)row)[k] = u;
    }
    if (OUT == 32) *(float2*)(row + 64) = make_float2(a0, a1);
    else           *(float*)(row + 32) = a0;
}

// ---------------- layer-1 node pass (IN=3, OUT=32, H=2, C=16) ---------------
__global__ __launch_bounds__(256) void node_pass1(const float* __restrict__ x,
                                                  const float* __restrict__ W,
                                                  const float* __restrict__ aw,
                                                  const float* __restrict__ dw,
                                                  int n) {
    __shared__ float sW[3 * 32];
    __shared__ float sA[32], sB[32];
    int t = threadIdx.x;
    if (t < 96) sW[t] = W[t];
    if (t < 32) { sA[t] = aw[t]; sB[t] = dw[t]; }
    __syncthreads();
    int i = blockIdx.x * 256 + t;
    if (i >= n) return;

    float x0 = x[3 * i], x1 = x[3 * i + 1], x2 = x[3 * i + 2];
    float h[32];
#pragma unroll
    for (int o = 0; o < 32; o++)
        h[o] = x0 * sW[o] + x1 * sW[32 + o] + x2 * sW[64 + o];

    float a0 = 0.f, a1 = 0.f, d0 = 0.f, d1 = 0.f;
#pragma unroll
    for (int c = 0; c < 16; c++) {
        a0 += h[c] * sA[c];           d0 += h[c] * sB[c];
        a1 += h[16 + c] * sA[16 + c]; d1 += h[16 + c] * sB[16 + c];
    }
    store_record<32>((char*)g_rec + (size_t)i * 128, h, a0, a1);
    g_adst[2 * i] = d0; g_adst[2 * i + 1] = d1;
}

// ---------------- node pass layers 2/3: divide + bias + elu + GEMM ----------
template <int IN, int OUT, int H, int STRIDE>
__global__ __launch_bounds__(256) void node_passN(const float* __restrict__ W,
                                                  const float* __restrict__ aw,
                                                  const float* __restrict__ dw,
                                                  const float* __restrict__ bias_prev,
                                                  int n) {
    __shared__ float sW[IN * OUT];
    __shared__ float sA[OUT], sB[OUT], sBias[IN];
    for (int j = threadIdx.x; j < IN * OUT; j += 256) sW[j] = W[j];
    if (threadIdx.x < OUT) { sA[threadIdx.x] = aw[threadIdx.x]; sB[threadIdx.x] = dw[threadIdx.x]; }
    if (threadIdx.x < IN)  sBias[threadIdx.x] = bias_prev[threadIdx.x];
    __syncthreads();
    int i = blockIdx.x * 256 + threadIdx.x;
    if (i >= n) return;

    float inv0 = 1.f / (g_sum[2 * i] + 1e-16f);
    float inv1 = 1.f / (g_sum[2 * i + 1] + 1e-16f);

    float feat[IN];
#pragma unroll
    for (int c = 0; c < IN; c++) {
        float v = g_agg[(size_t)i * IN + c] * ((c < IN / 2) ? inv0 : inv1) + sBias[c];
        feat[c] = (v > 0.f) ? v : expm1f(v);   // elu
    }

    float h[OUT];
#pragma unroll
    for (int o = 0; o < OUT; o++) h[o] = 0.f;
#pragma unroll
    for (int c = 0; c < IN; c++) {
        float f = feat[c];
#pragma unroll
        for (int o = 0; o < OUT; o++) h[o] += f * sW[c * OUT + o];
    }

    float a0 = 0.f, a1 = 0.f, d0 = 0.f, d1 = 0.f;
    if (H == 2) {
#pragma unroll
        for (int c = 0; c < 16; c++) {
            a0 += h[c] * sA[c];            d0 += h[c] * sB[c];
            a1 += h[16 + c] * sA[16 + c];  d1 += h[16 + c] * sB[16 + c];
        }
    } else {
#pragma unroll
        for (int c = 0; c < 16; c++) { a0 += h[c] * sA[c]; d0 += h[c] * sB[c]; }
    }
    store_record<OUT>((char*)g_rec + (size_t)i * STRIDE, h, a0, a1);
    g_adst[2 * i] = d0; g_adst[2 * i + 1] = (H == 2) ? d1 : 0.f;
}

// ---------------- edge pass, layers 1-2 (OUT=32, H=2) -----------------------
// 4 lanes per edge read one 128B record (h via uint4, asrc via direct float2
// load of the same line). 8 independent edge chains per warp, no intra-loop
// warp sync. Lanes of a group hold duplicate ws; reduction starts at off=4.
__global__ __launch_bounds__(256) void edge_csr32(int n) {
    int warp = (blockIdx.x * 256 + threadIdx.x) >> 5;
    if (warp >= n) return;
    int d = warp;
    int lane = threadIdx.x & 31;
    int grp = lane >> 2;           // 8 edges in flight
    int l = lane & 3;

    int start = g_off[d];
    int end   = g_off[d + 1];
    float2 ad = *(const float2*)(g_adst + 2 * d);

    float acc[8];
#pragma unroll
    for (int k = 0; k < 8; k++) acc[k] = 0.f;
    float ws0 = 0.f, ws1 = 0.f;

    for (int e = start + grp; e < end; e += 8) {
        int s = g_csr_src[e];
        const char* rp = (const char*)g_rec + (size_t)s * 128;
        uint4 u = ((const uint4*)rp)[l];
        float2 as = *(const float2*)(rp + 64);   // same line, broadcast in group

        float e0 = as.x + ad.x;
        e0 = fmaxf(e0, 0.2f * e0);               // leaky_relu(., 0.2)
        float w0 = __expf(e0);
        float e1 = as.y + ad.y;
        e1 = fmaxf(e1, 0.2f * e1);
        float w1 = __expf(e1);
        ws0 += w0; ws1 += w1;                    // duplicated across 4 lanes

        float w = (l >= 2) ? w1 : w0;            // l=0,1 head0; l=2,3 head1
        float2 f0 = __half22float2(*(__half2*)&u.x);
        float2 f1 = __half22float2(*(__half2*)&u.y);
        float2 f2 = __half22float2(*(__half2*)&u.z);
        float2 f3 = __half22float2(*(__half2*)&u.w);
        acc[0] += f0.x * w; acc[1] += f0.y * w;
        acc[2] += f1.x * w; acc[3] += f1.y * w;
        acc[4] += f2.x * w; acc[5] += f2.y * w;
        acc[6] += f3.x * w; acc[7] += f3.y * w;
    }

    // reduce across the 8 edge groups (stride >= 4 keeps within-group dupes out)
#pragma unroll
    for (int off = 4; off < 32; off <<= 1) {
#pragma unroll
        for (int k = 0; k < 8; k++)
            acc[k] += __shfl_xor_sync(0xffffffffu, acc[k], off);
        ws0 += __shfl_xor_sync(0xffffffffu, ws0, off);
        ws1 += __shfl_xor_sync(0xffffffffu, ws1, off);
    }

    if (lane < 4) {
        float* op = g_agg + (size_t)d * 32 + lane * 8;
        ((float4*)op)[0] = make_float4(acc[0], acc[1], acc[2], acc[3]);
        ((float4*)op)[1] = make_float4(acc[4], acc[5], acc[6], acc[7]);
    }
    if (lane == 0) {
        g_sum[2 * d] = ws0;
        g_sum[2 * d + 1] = ws1;
    }
}

// ---------------- edge pass layer 3 (OUT=16, H=1) + fused finalize ----------
// 2 lanes per edge read one 64B record; 16 chains per warp. Epilogue does
// divide + bias + elu -> embeddings and the sigmoid output head in-warp.
__global__ __launch_bounds__(256) void edge_csr16_fin(const float* __restrict__ b3,
                                                      const float* __restrict__ Wout,
                                                      const float* __restrict__ bout,
                                                      float* __restrict__ out, int n) {
    int warp = (blockIdx.x * 256 + threadIdx.x) >> 5;
    if (warp >= n) return;
    int d = warp;
    int lane = threadIdx.x & 31;
    int grp = lane >> 1;           // 16 edges in flight
    int l = lane & 1;

    int start = g_off[d];
    int end   = g_off[d + 1];
    float adx = g_adst[2 * d];

    float acc[8];
#pragma unroll
    for (int k = 0; k < 8; k++) acc[k] = 0.f;
    float ws0 = 0.f;

    for (int e = start + grp; e < end; e += 16) {
        int s = g_csr_src[e];
        const char* rp = (const char*)g_rec + (size_t)s * 64;
        uint4 u = ((const uint4*)rp)[l];
        float asx = *(const float*)(rp + 32);    // same line, broadcast in group

        float e0 = asx + adx;
        e0 = fmaxf(e0, 0.2f * e0);
        float w0 = __expf(e0);
        ws0 += w0;                               // duplicated across 2 lanes

        float2 f0 = __half22float2(*(__half2*)&u.x);
        float2 f1 = __half22float2(*(__half2*)&u.y);
        float2 f2 = __half22float2(*(__half2*)&u.z);
        float2 f3 = __half22float2(*(__half2*)&u.w);
        acc[0] += f0.x * w0; acc[1] += f0.y * w0;
        acc[2] += f1.x * w0; acc[3] += f1.y * w0;
        acc[4] += f2.x * w0; acc[5] += f2.y * w0;
        acc[6] += f3.x * w0; acc[7] += f3.y * w0;
    }

#pragma unroll
    for (int off = 2; off < 32; off <<= 1) {
#pragma unroll
        for (int k = 0; k < 8; k++)
            acc[k] += __shfl_xor_sync(0xffffffffu, acc[k], off);
        ws0 += __shfl_xor_sync(0xffffffffu, ws0, off);
    }

    // lanes 0,1 hold agg2[d, l*8 .. l*8+7] and full ws0: fused finalize
    float inv = 1.f / (ws0 + 1e-16f);
    float part = 0.f;
    float v[8];
#pragma unroll
    for (int c = 0; c < 8; c++) {
        float t = acc[c] * inv + __ldg(b3 + l * 8 + c);
        t = (t > 0.f) ? t : expm1f(t);           // elu -> embedding
        v[c] = t;
        part += t * __ldg(Wout + l * 8 + c);
    }
    part += __shfl_xor_sync(0xffffffffu, part, 1);
    if (lane < 2) {
        float* eo = out + n + (size_t)d * 16 + l * 8;
        ((float4*)eo)[0] = make_float4(v[0], v[1], v[2], v[3]);
        ((float4*)eo)[1] = make_float4(v[4], v[5], v[6], v[7]);
    }
    if (lane == 0)
        out[d] = 1.f / (1.f + __expf(-(part + __ldg(bout))));
}

// ---------------- launch -----------------------------------------------------
extern "C" void kernel_launch(void* const* d_in, const int* in_sizes, int n_in,
                              void* d_out, int out_size) {
    const float* x  = (const float*)d_in[0];
    const void*  ei = d_in[1];
    const float *W1 = (const float*)d_in[2],  *as1 = (const float*)d_in[3],
                *ad1 = (const float*)d_in[4], *b1  = (const float*)d_in[5];
    const float *W2 = (const float*)d_in[6],  *as2 = (const float*)d_in[7],
                *ad2 = (const float*)d_in[8], *b2  = (const float*)d_in[9];
    const float *W3 = (const float*)d_in[10], *as3 = (const float*)d_in[11],
                *ad3 = (const float*)d_in[12], *b3 = (const float*)d_in[13];
    const float *Wout = (const float*)d_in[14], *bout = (const float*)d_in[15];

    int n    = in_sizes[0] / 3;
    int E    = in_sizes[1] / 2;
    int etot = E + n;
    int nb = (n + 255) / 256;
    int eb = (etot + 255) / 256;
    int wb = (n * 32 + 255) / 256;          // warp-per-node grids
    int sb = (n + SCAN_B - 1) / SCAN_B;

    // ---- CSR build (graph is layer-invariant; built once per launch) ----
    probe_zero<<<nb, 256>>>((const int*)ei, n);
    hist<<<eb, 256>>>(ei, E, n);
    scan1<<<sb, SCAN_B>>>(n);
    scan2<<<1, 256>>>(sb);
    scan3<<<nb, 256>>>(n, etot);
    scatter<<<eb, 256>>>(ei, E, n);

    // ---- layer 1 ----
    node_pass1<<<nb, 256>>>(x, W1, as1, ad1, n);
    edge_csr32<<<wb, 256>>>(n);

    // ---- layer 2 ----
    node_passN<32, 32, 2, 128><<<nb, 256>>>(W2, as2, ad2, b1, n);
    edge_csr32<<<wb, 256>>>(n);

    // ---- layer 3 ----
    node_passN<32, 16, 1, 64><<<nb, 256>>>(W3, as3, ad3, b2, n);
    edge_csr16_fin<<<wb, 256>>>(b3, Wout, bout, (float*)d_out, n);
}

// round 10
// speedup vs baseline: 1.5197x; 1.5197x over previous
#include <cuda_runtime.h>

#define NN    100000
#define NE    3200000
#define ETOT  (NE + NN)
#define SCAN_B 512
#define NBLK   ((NN + SCAN_B - 1) / SCAN_B)   // 196

// ---------------- scratch (device globals; allocation-free) ----------------
__device__ __align__(16) float g_h[NN * 32];      // per-node transformed features (fp32)
__device__ __align__(16) float g_agg[NN * 32];    // aggregated output, layers 1-2
__device__ __align__(8)  float g_asrc[NN * 2];    // alpha_src per node per head
__device__ __align__(8)  float g_adst[NN * 2];    // alpha_dst per node per head
__device__ __align__(8)  float g_sum[NN * 2];     // softmax denominator (layers 1-2)
__device__ int g_csr_src[ETOT];                   // src ids grouped by dst
__device__ int g_cnt[NN];
__device__ int g_off[NN + 1];
__device__ int g_cur[NN];
__device__ int g_bsum[NBLK];
__device__ int g_boff[NBLK];
__device__ int g_is64;

// ---------------- probe dtype (block 0) + zero counts (all blocks) ----------
__global__ __launch_bounds__(256) void probe_zero(const int* __restrict__ ei32, int n) {
    int i = blockIdx.x * 256 + threadIdx.x;
    if (i < n) g_cnt[i] = 0;
    if (blockIdx.x == 0) {
        __shared__ int nz;
        if (threadIdx.x == 0) nz = 0;
        __syncthreads();
        // int64 arrays of small values have zero odd 32-bit words
        if (ei32[2 * threadIdx.x + 1] != 0) atomicOr(&nz, 1);
        __syncthreads();
        if (threadIdx.x == 0) g_is64 = (nz == 0) ? 1 : 0;
    }
}

// ---------------- dst histogram straight from edge_index --------------------
__global__ __launch_bounds__(256) void hist(const void* __restrict__ ei, int E, int n) {
    int i = blockIdx.x * 256 + threadIdx.x;
    int d;
    if (i < E) {
        d = g_is64 ? (int)((const long long*)ei)[E + i] : ((const int*)ei)[E + i];
    } else if (i < E + n) {
        d = i - E;
    } else return;
    atomicAdd(&g_cnt[d], 1);
}

// ---------------- 3-kernel exclusive scan of g_cnt -> g_off -----------------
__global__ __launch_bounds__(SCAN_B) void scan1(int n) {
    __shared__ int sm[SCAN_B];
    int t = threadIdx.x, i = blockIdx.x * SCAN_B + t;
    int v = (i < n) ? g_cnt[i] : 0;
    sm[t] = v; __syncthreads();
#pragma unroll
    for (int o = 1; o < SCAN_B; o <<= 1) {
        int x = (t >= o) ? sm[t - o] : 0;
        __syncthreads();
        sm[t] += x;
        __syncthreads();
    }
    if (i < n) g_off[i] = sm[t] - v;
    if (t == SCAN_B - 1) g_bsum[blockIdx.x] = sm[t];
}

__global__ void scan2(int nb) {
    __shared__ int sm[256];
    int t = threadIdx.x;
    int v = (t < nb) ? g_bsum[t] : 0;
    sm[t] = v; __syncthreads();
#pragma unroll
    for (int o = 1; o < 256; o <<= 1) {
        int x = (t >= o) ? sm[t - o] : 0;
        __syncthreads();
        sm[t] += x;
        __syncthreads();
    }
    if (t < nb) g_boff[t] = sm[t] - v;
}

__global__ __launch_bounds__(256) void scan3(int n, int etot) {
    int i = blockIdx.x * 256 + threadIdx.x;
    if (i < n) {
        int v = g_off[i] + g_boff[i / SCAN_B];
        g_off[i] = v;
        g_cur[i] = v;
    }
    if (i == 0) g_off[n] = etot;
}

// ---------------- scatter straight from edge_index --------------------------
__global__ __launch_bounds__(256) void scatter(const void* __restrict__ ei, int E, int n) {
    int i = blockIdx.x * 256 + threadIdx.x;
    int s, d;
    if (i < E) {
        if (g_is64) {
            const long long* p = (const long long*)ei;
            s = (int)p[i]; d = (int)p[E + i];
        } else {
            const int* p = (const int*)ei;
            s = p[i]; d = p[E + i];
        }
    } else if (i < E + n) {
        s = d = i - E;
    } else return;
    int p = atomicAdd(&g_cur[d], 1);
    g_csr_src[p] = s;
}

// ---------------- layer-1 node pass (IN=3, OUT=32, H=2, C=16) ---------------
__global__ __launch_bounds__(256) void node_pass1(const float* __restrict__ x,
                                                  const float* __restrict__ W,
                                                  const float* __restrict__ aw,
                                                  const float* __restrict__ dw,
                                                  int n) {
    __shared__ float sW[3 * 32];
    __shared__ float sA[32], sB[32];
    int t = threadIdx.x;
    if (t < 96) sW[t] = W[t];
    if (t < 32) { sA[t] = aw[t]; sB[t] = dw[t]; }
    __syncthreads();
    int i = blockIdx.x * 256 + t;
    if (i >= n) return;

    float x0 = x[3 * i], x1 = x[3 * i + 1], x2 = x[3 * i + 2];
    float h[32];
#pragma unroll
    for (int o = 0; o < 32; o++)
        h[o] = x0 * sW[o] + x1 * sW[32 + o] + x2 * sW[64 + o];

    float4* hp = (float4*)(g_h + (size_t)i * 32);
#pragma unroll
    for (int k = 0; k < 8; k++)
        hp[k] = make_float4(h[4 * k], h[4 * k + 1], h[4 * k + 2], h[4 * k + 3]);

    float a0 = 0.f, a1 = 0.f, d0 = 0.f, d1 = 0.f;
#pragma unroll
    for (int c = 0; c < 16; c++) {
        a0 += h[c] * sA[c];           d0 += h[c] * sB[c];
        a1 += h[16 + c] * sA[16 + c]; d1 += h[16 + c] * sB[16 + c];
    }
    g_asrc[2 * i] = a0; g_asrc[2 * i + 1] = a1;
    g_adst[2 * i] = d0; g_adst[2 * i + 1] = d1;
}

// ---------------- node pass layers 2/3: divide + bias + elu + GEMM ----------
template <int IN, int OUT, int H>
__global__ __launch_bounds__(256) void node_passN(const float* __restrict__ W,
                                                  const float* __restrict__ aw,
                                                  const float* __restrict__ dw,
                                                  const float* __restrict__ bias_prev,
                                                  int n) {
    __shared__ float sW[IN * OUT];
    __shared__ float sA[OUT], sB[OUT], sBias[IN];
    for (int j = threadIdx.x; j < IN * OUT; j += 256) sW[j] = W[j];
    if (threadIdx.x < OUT) { sA[threadIdx.x] = aw[threadIdx.x]; sB[threadIdx.x] = dw[threadIdx.x]; }
    if (threadIdx.x < IN)  sBias[threadIdx.x] = bias_prev[threadIdx.x];
    __syncthreads();
    int i = blockIdx.x * 256 + threadIdx.x;
    if (i >= n) return;

    float inv0 = 1.f / (g_sum[2 * i] + 1e-16f);
    float inv1 = 1.f / (g_sum[2 * i + 1] + 1e-16f);

    float feat[IN];
#pragma unroll
    for (int c = 0; c < IN; c++) {
        float v = g_agg[(size_t)i * IN + c] * ((c < IN / 2) ? inv0 : inv1) + sBias[c];
        feat[c] = (v > 0.f) ? v : expm1f(v);   // elu
    }

    float h[OUT];
#pragma unroll
    for (int o = 0; o < OUT; o++) h[o] = 0.f;
#pragma unroll
    for (int c = 0; c < IN; c++) {
        float f = feat[c];
#pragma unroll
        for (int o = 0; o < OUT; o++) h[o] += f * sW[c * OUT + o];
    }

    float4* hp = (float4*)(g_h + (size_t)i * OUT);
#pragma unroll
    for (int k = 0; k < OUT / 4; k++)
        hp[k] = make_float4(h[4 * k], h[4 * k + 1], h[4 * k + 2], h[4 * k + 3]);

    if (H == 2) {
        float a0 = 0.f, a1 = 0.f, d0 = 0.f, d1 = 0.f;
#pragma unroll
        for (int c = 0; c < 16; c++) {
            a0 += h[c] * sA[c];            d0 += h[c] * sB[c];
            a1 += h[16 + c] * sA[16 + c];  d1 += h[16 + c] * sB[16 + c];
        }
        g_asrc[2 * i] = a0; g_asrc[2 * i + 1] = a1;
        g_adst[2 * i] = d0; g_adst[2 * i + 1] = d1;
    } else {
        float a0 = 0.f, d0 = 0.f;
#pragma unroll
        for (int c = 0; c < 16; c++) { a0 += h[c] * sA[c]; d0 += h[c] * sB[c]; }
        g_asrc[2 * i] = a0; g_asrc[2 * i + 1] = 0.f;
        g_adst[2 * i] = d0; g_adst[2 * i + 1] = 0.f;
    }
}

// ---------------- CSR edge pass, layers 1-2 (OUT=32, H=2) -------------------
// Warp per dst, 8 lanes per edge, 4 independent edge chains, shfl only at the
// end. asrc/adst from small dense arrays (L1-friendly). No atomics.
__global__ __launch_bounds__(256) void edge_csr32(int n) {
    int warp = (blockIdx.x * 256 + threadIdx.x) >> 5;
    if (warp >= n) return;
    int d = warp;
    int lane = threadIdx.x & 31;
    int grp = lane >> 3;           // 4 edges in flight
    int l = lane & 7;

    int start = g_off[d];
    int end   = g_off[d + 1];
    float2 ad = *(const float2*)(g_adst + 2 * d);

    float ax = 0.f, ay = 0.f, az = 0.f, aw_ = 0.f;
    float ws0 = 0.f, ws1 = 0.f;

    for (int e = start + grp; e < end; e += 4) {
        int s = g_csr_src[e];
        float2 as = *(const float2*)(g_asrc + 2 * s);

        float e0 = as.x + ad.x;
        e0 = fmaxf(e0, 0.2f * e0);             // leaky_relu(., 0.2)
        float w0 = __expf(e0);
        float e1 = as.y + ad.y;
        e1 = fmaxf(e1, 0.2f * e1);
        float w1 = __expf(e1);
        if (l == 0) { ws0 += w0; ws1 += w1; }

        float w = (l >= 4) ? w1 : w0;          // l=0..3 head0; l=4..7 head1
        float4 v = ((const float4*)(g_h + (size_t)s * 32))[l];
        ax += v.x * w; ay += v.y * w; az += v.z * w; aw_ += v.w * w;
    }

    // reduce across the 4 edge groups (same l)
#pragma unroll
    for (int off = 8; off < 32; off <<= 1) {
        ax  += __shfl_xor_sync(0xffffffffu, ax,  off);
        ay  += __shfl_xor_sync(0xffffffffu, ay,  off);
        az  += __shfl_xor_sync(0xffffffffu, az,  off);
        aw_ += __shfl_xor_sync(0xffffffffu, aw_, off);
        ws0 += __shfl_xor_sync(0xffffffffu, ws0, off);
        ws1 += __shfl_xor_sync(0xffffffffu, ws1, off);
    }

    if (lane < 8)
        ((float4*)(g_agg + (size_t)d * 32))[lane] = make_float4(ax, ay, az, aw_);
    if (lane == 0) {
        g_sum[2 * d] = ws0;
        g_sum[2 * d + 1] = ws1;
    }
}

// ---------------- edge pass layer 3 (OUT=16, H=1) + fused finalize ----------
// 4 lanes per edge, 8 chains. Epilogue: divide + bias + elu -> embeddings and
// the sigmoid output head, all in-warp (agg2 never touches memory).
__global__ __launch_bounds__(256) void edge_csr16_fin(const float* __restrict__ b3,
                                                      const float* __restrict__ Wout,
                                                      const float* __restrict__ bout,
                                                      float* __restrict__ out, int n) {
    int warp = (blockIdx.x * 256 + threadIdx.x) >> 5;
    if (warp >= n) return;
    int d = warp;
    int lane = threadIdx.x & 31;
    int grp = lane >> 2;           // 8 edges in flight
    int l = lane & 3;

    int start = g_off[d];
    int end   = g_off[d + 1];
    float adx = g_adst[2 * d];

    float ax = 0.f, ay = 0.f, az = 0.f, aw_ = 0.f;
    float ws0 = 0.f;

    for (int e = start + grp; e < end; e += 8) {
        int s = g_csr_src[e];
        float asx = g_asrc[2 * s];

        float e0 = asx + adx;
        e0 = fmaxf(e0, 0.2f * e0);
        float w0 = __expf(e0);
        if (l == 0) ws0 += w0;

        float4 v = ((const float4*)(g_h + (size_t)s * 16))[l];
        ax += v.x * w0; ay += v.y * w0; az += v.z * w0; aw_ += v.w * w0;
    }

#pragma unroll
    for (int off = 4; off < 32; off <<= 1) {
        ax  += __shfl_xor_sync(0xffffffffu, ax,  off);
        ay  += __shfl_xor_sync(0xffffffffu, ay,  off);
        az  += __shfl_xor_sync(0xffffffffu, az,  off);
        aw_ += __shfl_xor_sync(0xffffffffu, aw_, off);
        ws0 += __shfl_xor_sync(0xffffffffu, ws0, off);
    }
    float ws = __shfl_sync(0xffffffffu, ws0, 0);   // broadcast total to all lanes

    // lanes 0-3 hold row cols [l*4, l*4+4): fused finalize
    float inv = 1.f / (ws + 1e-16f);
    float v0 = ax * inv + __ldg(b3 + 4 * l + 0);
    float v1 = ay * inv + __ldg(b3 + 4 * l + 1);
    float v2 = az * inv + __ldg(b3 + 4 * l + 2);
    float v3 = aw_ * inv + __ldg(b3 + 4 * l + 3);
    v0 = (v0 > 0.f) ? v0 : expm1f(v0);
    v1 = (v1 > 0.f) ? v1 : expm1f(v1);
    v2 = (v2 > 0.f) ? v2 : expm1f(v2);
    v3 = (v3 > 0.f) ? v3 : expm1f(v3);

    float part = v0 * __ldg(Wout + 4 * l + 0) + v1 * __ldg(Wout + 4 * l + 1)
               + v2 * __ldg(Wout + 4 * l + 2) + v3 * __ldg(Wout + 4 * l + 3);
    part += __shfl_xor_sync(0xffffffffu, part, 1);
    part += __shfl_xor_sync(0xffffffffu, part, 2);

    if (lane < 4)
        ((float4*)(out + n + (size_t)d * 16))[l] = make_float4(v0, v1, v2, v3);
    if (lane == 0)
        out[d] = 1.f / (1.f + __expf(-(part + __ldg(bout))));
}

// ---------------- launch -----------------------------------------------------
extern "C" void kernel_launch(void* const* d_in, const int* in_sizes, int n_in,
                              void* d_out, int out_size) {
    const float* x  = (const float*)d_in[0];
    const void*  ei = d_in[1];
    const float *W1 = (const float*)d_in[2],  *as1 = (const float*)d_in[3],
                *ad1 = (const float*)d_in[4], *b1  = (const float*)d_in[5];
    const float *W2 = (const float*)d_in[6],  *as2 = (const float*)d_in[7],
                *ad2 = (const float*)d_in[8], *b2  = (const float*)d_in[9];
    const float *W3 = (const float*)d_in[10], *as3 = (const float*)d_in[11],
                *ad3 = (const float*)d_in[12], *b3 = (const float*)d_in[13];
    const float *Wout = (const float*)d_in[14], *bout = (const float*)d_in[15];

    int n    = in_sizes[0] / 3;
    int E    = in_sizes[1] / 2;
    int etot = E + n;
    int nb = (n + 255) / 256;
    int eb = (etot + 255) / 256;
    int wb = (n * 32 + 255) / 256;          // warp-per-node grids
    int sb = (n + SCAN_B - 1) / SCAN_B;

    // ---- CSR build (graph is layer-invariant; built once per launch) ----
    probe_zero<<<nb, 256>>>((const int*)ei, n);
    hist<<<eb, 256>>>(ei, E, n);
    scan1<<<sb, SCAN_B>>>(n);
    scan2<<<1, 256>>>(sb);
    scan3<<<nb, 256>>>(n, etot);
    scatter<<<eb, 256>>>(ei, E, n);

    // ---- layer 1 ----
    node_pass1<<<nb, 256>>>(x, W1, as1, ad1, n);
    edge_csr32<<<wb, 256>>>(n);

    // ---- layer 2 ----
    node_passN<32, 32, 2><<<nb, 256>>>(W2, as2, ad2, b1, n);
    edge_csr32<<<wb, 256>>>(n);

    // ---- layer 3 + fused output head ----
    node_passN<32, 16, 1><<<nb, 256>>>(W3, as3, ad3, b2, n);
    edge_csr16_fin<<<wb, 256>>>(b3, Wout, bout, (float*)d_out, n);
}